// round 14
// baseline (speedup 1.0000x reference)
#include <cuda_runtime.h>
#include <cuda_bf16.h>
#include <cstdint>

#define NN 1024
#define DD 512
#define CC 384
#define SS 49
#define NCS (NN*CC*SS)   // 19267584
#define FIXM 90.0f       // fixed LSE offset; logits ~N(0,22.6), overflow needs >178

// scratch (static device arrays — no runtime allocation)
__device__ __align__(16) __nv_bfloat16 g_fs[NN*CC];              // f[:,0:384]
__device__ __align__(16) __nv_bfloat16 g_fm[NN*128];             // f[:,384:512]
__device__ __align__(16) __nv_bfloat16 g_prev[(size_t)SS*NN*CC]; // pos spatial
__device__ __align__(16) __nv_bfloat16 g_cur[(size_t)SS*NN*CC];  // pred spatial
__device__ __align__(16) __nv_bfloat16 g_mcp[NN*128];            // [m_prev,c_prev]
__device__ __align__(16) __nv_bfloat16 g_mcc[NN*128];            // [m_t,c_t]
__device__ float g_bias[2][NN*NN];                               // 8MB fp32
__device__ float g_pl[2*SS*8*128*2];                             // partial sumexp (offset FIXM)
__device__ float g_pd[2*SS*NN];                                  // diag
__device__ float g_ce[2*SS];

__device__ __forceinline__ void cp16(uint32_t dst, const void* src) {
    asm volatile("cp.async.cg.shared.global [%0], [%1], 16;\n" :: "r"(dst), "l"(src));
}

// ---------------------------------------------------------------------------
__global__ void k_convert_f(const float* __restrict__ f) {
    int i = blockIdx.x * blockDim.x + threadIdx.x;
    if (i >= NN*DD) return;
    int row = i >> 9, d = i & 511;
    __nv_bfloat16 v = __float2bfloat16(f[i]);
    if (d < CC) g_fs[row*CC + d] = v; else g_fm[row*128 + d - CC] = v;
}

// mc tables, bf16 (no s-broadcast)
__global__ void k_mc(const float* __restrict__ mp, const float* __restrict__ cp,
                     const float* __restrict__ mt, const float* __restrict__ ct) {
    int j = blockIdx.x;
    int dd = threadIdx.x;  // 0..127
    float vp = (dd < 64) ? mp[j*64 + dd] : cp[j*64 + dd - 64];
    float vc = (dd < 64) ? mt[j*64 + dd] : ct[j*64 + dd - 64];
    g_mcp[j*128 + dd] = __float2bfloat16(vp);
    g_mcc[j*128 + dd] = __float2bfloat16(vc);
}

// dst[s][j][d] = x[j][d][s] (d<384), bf16; also raw fp32 copy. grid (1024,2)
__global__ void k_spatial(const float* __restrict__ xc,
                          const float* __restrict__ xp,
                          float* __restrict__ out) {
    __shared__ float sbuf[32*SS];
    const int isPred = blockIdx.y;
    const float* x = isPred ? xc : xp;
    __nv_bfloat16* dst = isPred ? g_cur : g_prev;
    float* outCopy = out + 1 + (size_t)isPred*NCS;
    int j = blockIdx.x;
    const float* xj = x + (size_t)j*CC*SS;
    float* oj = outCopy + (size_t)j*CC*SS;
    for (int d0 = 0; d0 < CC; d0 += 32) {
        for (int t = threadIdx.x; t < 32*SS; t += blockDim.x) {
            float v = xj[d0*SS + t];
            sbuf[t] = v;
            oj[d0*SS + t] = v;
        }
        __syncthreads();
        for (int t = threadIdx.x; t < 32*SS; t += blockDim.x) {
            int ss = t >> 5;
            int dd = t & 31;
            dst[((size_t)(ss*NN + j))*CC + d0 + dd] = __float2bfloat16(sbuf[dd*SS + ss]);
        }
        __syncthreads();
    }
}

// ---------------------------------------------------------------------------
// bias[which][i][j] = (which? mcc[i] : fm[i]) . mcp[j], K=128. grid (8,8,2).
__global__ void __launch_bounds__(256) k_bias() {
    const int iBase = blockIdx.x * 128;
    const int jBase = blockIdx.y * 128;
    const int which = blockIdx.z;
    const int tid  = threadIdx.x;
    const int lane = tid & 31;
    const int warp = tid >> 5;
    const int wRow = warp >> 2;
    const int wCol = warp & 3;

    __shared__ __align__(16) __nv_bfloat16 sA[128][72];
    __shared__ __align__(16) __nv_bfloat16 sB[128][72];

    const __nv_bfloat16* gA = (which ? g_mcc : g_fm) + (size_t)iBase * 128;
    const __nv_bfloat16* gB = g_mcp + (size_t)jBase * 128;

    float acc[4][4][4];
    #pragma unroll
    for (int mf = 0; mf < 4; mf++)
        #pragma unroll
        for (int nf = 0; nf < 4; nf++)
            #pragma unroll
            for (int v = 0; v < 4; v++) acc[mf][nf][v] = 0.f;

    for (int kt = 0; kt < 2; ++kt) {
        __syncthreads();
        #pragma unroll
        for (int p = 0; p < 4; ++p) {
            int id = tid + p * 256;
            int r  = id >> 3;
            int ck = id & 7;
            *reinterpret_cast<int4*>(&sA[r][ck*8]) =
                *(reinterpret_cast<const int4*>(gA + (size_t)r*128 + kt*64) + ck);
            *reinterpret_cast<int4*>(&sB[r][ck*8]) =
                *(reinterpret_cast<const int4*>(gB + (size_t)r*128 + kt*64) + ck);
        }
        __syncthreads();
        #pragma unroll
        for (int ks = 0; ks < 4; ++ks) {
            uint32_t aF[4][4], bF[4][2];
            #pragma unroll
            for (int mf = 0; mf < 4; mf++) {
                int row = wRow*64 + mf*16 + (lane & 15);
                int col = ks*16 + ((lane >> 4) << 3);
                uint32_t addr = (uint32_t)__cvta_generic_to_shared(&sA[row][col]);
                asm volatile("ldmatrix.sync.aligned.m8n8.x4.shared.b16 {%0,%1,%2,%3}, [%4];"
                    : "=r"(aF[mf][0]), "=r"(aF[mf][1]), "=r"(aF[mf][2]), "=r"(aF[mf][3])
                    : "r"(addr));
            }
            #pragma unroll
            for (int nf = 0; nf < 4; nf++) {
                int row = wCol*32 + nf*8 + (lane & 7);
                int col = ks*16 + (((lane >> 3) & 1) << 3);
                uint32_t addr = (uint32_t)__cvta_generic_to_shared(&sB[row][col]);
                asm volatile("ldmatrix.sync.aligned.m8n8.x2.shared.b16 {%0,%1}, [%2];"
                    : "=r"(bF[nf][0]), "=r"(bF[nf][1]) : "r"(addr));
            }
            #pragma unroll
            for (int mf = 0; mf < 4; mf++)
                #pragma unroll
                for (int nf = 0; nf < 4; nf++) {
                    float* c = acc[mf][nf];
                    asm volatile("mma.sync.aligned.m16n8k16.row.col.f32.bf16.bf16.f32 "
                        "{%0,%1,%2,%3}, {%4,%5,%6,%7}, {%8,%9}, {%0,%1,%2,%3};"
                        : "+f"(c[0]), "+f"(c[1]), "+f"(c[2]), "+f"(c[3])
                        : "r"(aF[mf][0]), "r"(aF[mf][1]), "r"(aF[mf][2]), "r"(aF[mf][3]),
                          "r"(bF[nf][0]), "r"(bF[nf][1]));
                }
        }
    }

    float* gOut = g_bias[which];
    #pragma unroll
    for (int mf = 0; mf < 4; mf++)
        #pragma unroll
        for (int h = 0; h < 2; h++) {
            int row = iBase + wRow*64 + mf*16 + h*8 + (lane >> 2);
            #pragma unroll
            for (int nf = 0; nf < 4; nf++) {
                int col = jBase + wCol*32 + nf*8 + (lane & 3)*2;
                float2 v = make_float2(acc[mf][nf][h*2], acc[mf][nf][h*2+1]);
                *reinterpret_cast<float2*>(gOut + (size_t)row*NN + col) = v;
            }
        }
}

// ---------------------------------------------------------------------------
// Fused GEMM(K=384) + bias + fixed-offset partial sumexp over a 512-wide j-half.
// Grid (32, 49): which=x&1, iTile=(x>>1)&7, jh=x>>4; s=y. 256 threads.
// CTA tile: 128 (i) x 256 (j per step, 2 steps). 8 warps as 2x4, warp 64x64.
#define ACHUNK 16384                // 128 rows * 128B
#define BCHUNK 32768                // 256 rows * 128B
#define OFF_A   0                   // 6 chunks = 98304
#define OFF_B   98304               // 3 chunks = 98304
#define OFF_DIAG 196608             // 128 floats
#define SMEM_MAIN 197120
// aliased into B ring after last chunk consumed:
#define OFF_SL  OFF_B               // 128*4 floats

__global__ void __launch_bounds__(256, 1) k_main() {
    extern __shared__ char smraw[];
    const uint32_t sb = (uint32_t)__cvta_generic_to_shared(smraw);

    const int which = blockIdx.x & 1;
    const int iTile = (blockIdx.x >> 1) & 7;
    const int jh    = blockIdx.x >> 4;
    const int s     = blockIdx.y;
    const int tid   = threadIdx.x;
    const int lane  = tid & 31;
    const int warp  = tid >> 5;
    const int wRow  = warp >> 2;    // 0..1 (i groups of 64)
    const int wCol  = warp & 3;     // 0..3 (j groups of 64)
    const int iBase = iTile * 128;
    const int jBase = jh * 512;

    const __nv_bfloat16* gA = which ? (g_cur + ((size_t)(s*NN) + iBase) * CC)
                                    : (g_fs + (size_t)iBase * CC);
    const __nv_bfloat16* gB0 = g_prev + ((size_t)(s*NN) + jBase) * CC;
    const float* gBias = g_bias[which] + (size_t)iBase * NN + jBase;

    // ---- A loads: 6 chunks x 1024 int4, 24 per thread (one commit group)
    #pragma unroll
    for (int p = 0; p < 24; ++p) {
        int id = tid + p * 256;
        int k6 = id >> 10, r = (id >> 3) & 127, u = id & 7;
        uint32_t dst = sb + OFF_A + k6*ACHUNK + r*128 + (((u ^ (r & 7))) << 4);
        cp16(dst, gA + (size_t)r*CC + k6*64 + u*8);
    }
    asm volatile("cp.async.commit_group;");

    auto loadB = [&](int c) {
        int jt = c / 6, kt = c % 6, slot = c % 3;
        #pragma unroll
        for (int p = 0; p < 8; ++p) {
            int id = tid + p * 256;
            int r = id >> 3, u = id & 7;
            uint32_t dst = sb + OFF_B + slot*BCHUNK + r*128 + (((u ^ (r & 7))) << 4);
            cp16(dst, gB0 + (size_t)(jt*256 + r)*CC + kt*64 + u*8);
        }
        asm volatile("cp.async.commit_group;");
    };
    loadB(0);
    loadB(1);

    // per-thread ldmatrix row precompute
    const int lane15 = lane & 15;
    const int hi     = lane >> 4;
    int aOff[4], aXor[4], bOff[4], bXor[4];
    #pragma unroll
    for (int mf = 0; mf < 4; mf++) {
        int r = wRow*64 + mf*16 + lane15;
        aOff[mf] = r * 128; aXor[mf] = r & 7;
    }
    #pragma unroll
    for (int nfp = 0; nfp < 4; nfp++) {
        int r = wCol*64 + nfp*16 + lane15;
        bOff[nfp] = r * 128; bXor[nfp] = r & 7;
    }

    // fixed-offset sumexp accumulators (no online max needed: logits ~N(0,22.6))
    float rl[4][2];
    #pragma unroll
    for (int mf = 0; mf < 4; mf++)
        #pragma unroll
        for (int h = 0; h < 2; h++) rl[mf][h] = 0.f;

    float* sDiag = reinterpret_cast<float*>(smraw + OFF_DIAG);
    const bool hasDiag = (jh == (iTile >> 2));
    const int diagJt  = (iTile & 3) >> 1;           // 256-block within half
    const int diagOfs = (iTile & 1) * 128;          // col offset within block

    int c = 0;
    for (int jt = 0; jt < 2; ++jt) {
        float acc[4][8][4];
        #pragma unroll
        for (int mf = 0; mf < 4; mf++)
            #pragma unroll
            for (int nf = 0; nf < 8; nf++)
                #pragma unroll
                for (int v = 0; v < 4; v++) acc[mf][nf][v] = 0.f;

        for (int kt = 0; kt < 6; ++kt, ++c) {
            // B(c) must be complete; B(c+1) may still be in flight.
            if (c < 11) asm volatile("cp.async.wait_group 1;");
            else        asm volatile("cp.async.wait_group 0;");
            __syncthreads();
            // Barrier guarantees all warps finished reading slot (c-1)%3 == (c+2)%3.
            if (c + 2 < 12) loadB(c + 2);

            const uint32_t abase = sb + OFF_A + kt*ACHUNK;
            const uint32_t bbase = sb + OFF_B + (c % 3)*BCHUNK;

            #pragma unroll
            for (int ks = 0; ks < 4; ++ks) {
                const int u = ks*2 + hi;
                uint32_t aF[4][4], bF[8][2];
                #pragma unroll
                for (int mf = 0; mf < 4; mf++) {
                    uint32_t addr = abase + aOff[mf] + ((u ^ aXor[mf]) << 4);
                    asm volatile("ldmatrix.sync.aligned.m8n8.x4.shared.b16 {%0,%1,%2,%3}, [%4];"
                        : "=r"(aF[mf][0]), "=r"(aF[mf][1]), "=r"(aF[mf][2]), "=r"(aF[mf][3])
                        : "r"(addr));
                }
                #pragma unroll
                for (int nfp = 0; nfp < 4; nfp++) {
                    uint32_t addr = bbase + bOff[nfp] + ((u ^ bXor[nfp]) << 4);
                    uint32_t b0, b1, b2, b3;
                    asm volatile("ldmatrix.sync.aligned.m8n8.x4.shared.b16 {%0,%1,%2,%3}, [%4];"
                        : "=r"(b0), "=r"(b1), "=r"(b2), "=r"(b3) : "r"(addr));
                    bF[nfp*2][0] = b0; bF[nfp*2][1] = b2;
                    bF[nfp*2+1][0] = b1; bF[nfp*2+1][1] = b3;
                }
                #pragma unroll
                for (int mf = 0; mf < 4; mf++)
                    #pragma unroll
                    for (int nf = 0; nf < 8; nf++) {
                        float* cc = acc[mf][nf];
                        asm volatile("mma.sync.aligned.m16n8k16.row.col.f32.bf16.bf16.f32 "
                            "{%0,%1,%2,%3}, {%4,%5,%6,%7}, {%8,%9}, {%0,%1,%2,%3};"
                            : "+f"(cc[0]), "+f"(cc[1]), "+f"(cc[2]), "+f"(cc[3])
                            : "r"(aF[mf][0]), "r"(aF[mf][1]), "r"(aF[mf][2]), "r"(aF[mf][3]),
                              "r"(bF[nf][0]), "r"(bF[nf][1]));
                    }
            }
        }

        // ---- bias add (fp32 from L2) + fixed-offset sumexp over this 256-col block
        #pragma unroll
        for (int mf = 0; mf < 4; mf++)
            #pragma unroll
            for (int h = 0; h < 2; h++) {
                int row = wRow*64 + mf*16 + h*8 + (lane >> 2);
                const float2* bp = reinterpret_cast<const float2*>(
                    gBias + (size_t)row*NN + jt*256 + wCol*64 + (lane & 3)*2);
                #pragma unroll
                for (int nf = 0; nf < 8; nf++) {
                    float2 b = __ldg(bp + nf*4);
                    acc[mf][nf][h*2]   += b.x;
                    acc[mf][nf][h*2+1] += b.y;
                }
            }

        const bool dt = hasDiag && (jt == diagJt);
        #pragma unroll
        for (int mf = 0; mf < 4; mf++) {
            #pragma unroll
            for (int h = 0; h < 2; h++) {
                float p = 0.f;
                #pragma unroll
                for (int nf = 0; nf < 8; nf++) {
                    p += __expf(acc[mf][nf][h*2]   - FIXM);
                    p += __expf(acc[mf][nf][h*2+1] - FIXM);
                }
                p += __shfl_xor_sync(0xffffffffu, p, 1);
                p += __shfl_xor_sync(0xffffffffu, p, 2);
                rl[mf][h] += p;
                if (dt) {
                    int rowLocal = wRow*64 + mf*16 + h*8 + (lane >> 2);
                    int clTarget = rowLocal + diagOfs;
                    #pragma unroll
                    for (int nf = 0; nf < 8; nf++) {
                        #pragma unroll
                        for (int q = 0; q < 2; q++) {
                            int col = wCol*64 + nf*8 + (lane & 3)*2 + q;
                            if (col == clTarget) sDiag[rowLocal] = acc[mf][nf][h*2+q];
                        }
                    }
                }
            }
        }
    }

    // ---- sum across warp-columns (alias B ring; all B consumed)
    __syncthreads();
    float* sL = reinterpret_cast<float*>(smraw + OFF_SL);
    if ((lane & 3) == 0) {
        #pragma unroll
        for (int mf = 0; mf < 4; mf++)
            #pragma unroll
            for (int h = 0; h < 2; h++) {
                int rowLocal = wRow*64 + mf*16 + h*8 + (lane >> 2);
                sL[rowLocal*4 + wCol] = rl[mf][h];
            }
    }
    __syncthreads();

    if (tid < 128) {
        float L = sL[tid*4+0] + sL[tid*4+1] + sL[tid*4+2] + sL[tid*4+3];
        size_t pidx = ((size_t)((which*SS + s)*8 + iTile)*128 + tid)*2 + jh;
        g_pl[pidx] = L;
        if (hasDiag)
            g_pd[(size_t)(which*SS + s)*NN + iBase + tid] = sDiag[tid];
    }
}

// ---------------------------------------------------------------------------
// combine halves: grid (98) = (which*49+s), 1024 threads = rows
__global__ void k_combine() {
    __shared__ float sr[32];
    const int ws = blockIdx.x;              // which*SS + s
    const int r  = threadIdx.x;             // 0..1023
    const int iTile = r >> 7, rowIn = r & 127;
    size_t base = ((size_t)(ws*8 + iTile)*128 + rowIn)*2;
    float L = g_pl[base] + g_pl[base+1];
    float ce = FIXM + logf(L) - g_pd[(size_t)ws*NN + r];
    #pragma unroll
    for (int o = 16; o > 0; o >>= 1) ce += __shfl_xor_sync(0xffffffffu, ce, o);
    if ((r & 31) == 0) sr[r >> 5] = ce;
    __syncthreads();
    if (r < 32) {
        float v = sr[r];
        #pragma unroll
        for (int o = 16; o > 0; o >>= 1) v += __shfl_xor_sync(0xffffffffu, v, o);
        if (r == 0) g_ce[ws] = v;
    }
}

__global__ void k_final(float* __restrict__ out) {
    int tid = threadIdx.x;
    float s = (tid < 2*SS) ? g_ce[tid] : 0.f;
    #pragma unroll
    for (int o = 16; o > 0; o >>= 1) s += __shfl_xor_sync(0xffffffffu, s, o);
    __shared__ float sr[4];
    if ((tid & 31) == 0) sr[tid >> 5] = s;
    __syncthreads();
    if (tid == 0) out[0] = (sr[0] + sr[1] + sr[2] + sr[3]) / (float)(SS * NN);
}

// ---------------------------------------------------------------------------
extern "C" void kernel_launch(void* const* d_in, const int* in_sizes, int n_in,
                              void* d_out, int out_size) {
    const float* f  = (const float*)d_in[0];
    const float* xc = (const float*)d_in[1];
    const float* xp = (const float*)d_in[2];
    const float* mt = (const float*)d_in[3];
    const float* mp = (const float*)d_in[4];
    const float* ct = (const float*)d_in[5];
    const float* cp = (const float*)d_in[6];
    float* out = (float*)d_out;

    cudaFuncSetAttribute(k_main, cudaFuncAttributeMaxDynamicSharedMemorySize, SMEM_MAIN);

    k_convert_f<<<(NN*DD + 255)/256, 256>>>(f);
    k_mc<<<NN, 128>>>(mp, cp, mt, ct);
    k_spatial<<<dim3(NN, 2), 256>>>(xc, xp, out);
    k_bias<<<dim3(8, 8, 2), 256>>>();
    k_main<<<dim3(32, SS), 256, SMEM_MAIN>>>();
    k_combine<<<2*SS, 1024>>>();
    k_final<<<1, 128>>>(out);
}

// round 15
// speedup vs baseline: 1.5459x; 1.5459x over previous
#include <cuda_runtime.h>
#include <cuda_bf16.h>
#include <cstdint>

#define NN 1024
#define DD 512
#define CC 384
#define SS 49
#define NCS (NN*CC*SS)   // 19267584

// scratch (static device arrays — no runtime allocation)
__device__ __align__(16) __nv_bfloat16 g_fs[NN*CC];              // f[:,0:384]
__device__ __align__(16) __nv_bfloat16 g_fm[NN*128];             // f[:,384:512]
__device__ __align__(16) __nv_bfloat16 g_prev[(size_t)SS*NN*CC]; // pos spatial
__device__ __align__(16) __nv_bfloat16 g_cur[(size_t)SS*NN*CC];  // pred spatial
__device__ __align__(16) __nv_bfloat16 g_mcp[NN*128];            // [m_prev,c_prev]
__device__ __align__(16) __nv_bfloat16 g_mcc[NN*128];            // [m_t,c_t]
__device__ float g_bias[2][NN*NN];                               // 8MB fp32
__device__ float g_pm[(size_t)2*SS*8*128*8];                     // block max per jt
__device__ float g_pl[(size_t)2*SS*8*128*8];                     // block sumexp per jt
__device__ float g_pd[2*SS*NN];                                  // diag
__device__ float g_ce[2*SS];

__device__ __forceinline__ void cp16(uint32_t dst, const void* src) {
    asm volatile("cp.async.cg.shared.global [%0], [%1], 16;\n" :: "r"(dst), "l"(src));
}

// ---------------------------------------------------------------------------
__global__ void k_convert_f(const float* __restrict__ f) {
    int i = blockIdx.x * blockDim.x + threadIdx.x;
    if (i >= NN*DD) return;
    int row = i >> 9, d = i & 511;
    __nv_bfloat16 v = __float2bfloat16(f[i]);
    if (d < CC) g_fs[row*CC + d] = v; else g_fm[row*128 + d - CC] = v;
}

__global__ void k_mc(const float* __restrict__ mp, const float* __restrict__ cp,
                     const float* __restrict__ mt, const float* __restrict__ ct) {
    int j = blockIdx.x;
    int dd = threadIdx.x;  // 0..127
    float vp = (dd < 64) ? mp[j*64 + dd] : cp[j*64 + dd - 64];
    float vc = (dd < 64) ? mt[j*64 + dd] : ct[j*64 + dd - 64];
    g_mcp[j*128 + dd] = __float2bfloat16(vp);
    g_mcc[j*128 + dd] = __float2bfloat16(vc);
}

// dst[s][j][d] = x[j][d][s] (d<384), bf16; also raw fp32 copy. grid (1024,2)
__global__ void k_spatial(const float* __restrict__ xc,
                          const float* __restrict__ xp,
                          float* __restrict__ out) {
    __shared__ float sbuf[32*SS];
    const int isPred = blockIdx.y;
    const float* x = isPred ? xc : xp;
    __nv_bfloat16* dst = isPred ? g_cur : g_prev;
    float* outCopy = out + 1 + (size_t)isPred*NCS;
    int j = blockIdx.x;
    const float* xj = x + (size_t)j*CC*SS;
    float* oj = outCopy + (size_t)j*CC*SS;
    for (int d0 = 0; d0 < CC; d0 += 32) {
        for (int t = threadIdx.x; t < 32*SS; t += blockDim.x) {
            float v = xj[d0*SS + t];
            sbuf[t] = v;
            oj[d0*SS + t] = v;
        }
        __syncthreads();
        for (int t = threadIdx.x; t < 32*SS; t += blockDim.x) {
            int ss = t >> 5;
            int dd = t & 31;
            dst[((size_t)(ss*NN + j))*CC + d0 + dd] = __float2bfloat16(sbuf[dd*SS + ss]);
        }
        __syncthreads();
    }
}

// ---------------------------------------------------------------------------
// bias[which][i][j] = (which? mcc[i] : fm[i]) . mcp[j], K=128. grid (8,8,2).
__global__ void __launch_bounds__(256) k_bias() {
    const int iBase = blockIdx.x * 128;
    const int jBase = blockIdx.y * 128;
    const int which = blockIdx.z;
    const int tid  = threadIdx.x;
    const int lane = tid & 31;
    const int warp = tid >> 5;
    const int wRow = warp >> 2;
    const int wCol = warp & 3;

    __shared__ __align__(16) __nv_bfloat16 sA[128][72];
    __shared__ __align__(16) __nv_bfloat16 sB[128][72];

    const __nv_bfloat16* gA = (which ? g_mcc : g_fm) + (size_t)iBase * 128;
    const __nv_bfloat16* gB = g_mcp + (size_t)jBase * 128;

    float acc[4][4][4];
    #pragma unroll
    for (int mf = 0; mf < 4; mf++)
        #pragma unroll
        for (int nf = 0; nf < 4; nf++)
            #pragma unroll
            for (int v = 0; v < 4; v++) acc[mf][nf][v] = 0.f;

    for (int kt = 0; kt < 2; ++kt) {
        __syncthreads();
        #pragma unroll
        for (int p = 0; p < 4; ++p) {
            int id = tid + p * 256;
            int r  = id >> 3;
            int ck = id & 7;
            *reinterpret_cast<int4*>(&sA[r][ck*8]) =
                *(reinterpret_cast<const int4*>(gA + (size_t)r*128 + kt*64) + ck);
            *reinterpret_cast<int4*>(&sB[r][ck*8]) =
                *(reinterpret_cast<const int4*>(gB + (size_t)r*128 + kt*64) + ck);
        }
        __syncthreads();
        #pragma unroll
        for (int ks = 0; ks < 4; ++ks) {
            uint32_t aF[4][4], bF[4][2];
            #pragma unroll
            for (int mf = 0; mf < 4; mf++) {
                int row = wRow*64 + mf*16 + (lane & 15);
                int col = ks*16 + ((lane >> 4) << 3);
                uint32_t addr = (uint32_t)__cvta_generic_to_shared(&sA[row][col]);
                asm volatile("ldmatrix.sync.aligned.m8n8.x4.shared.b16 {%0,%1,%2,%3}, [%4];"
                    : "=r"(aF[mf][0]), "=r"(aF[mf][1]), "=r"(aF[mf][2]), "=r"(aF[mf][3])
                    : "r"(addr));
            }
            #pragma unroll
            for (int nf = 0; nf < 4; nf++) {
                int row = wCol*32 + nf*8 + (lane & 7);
                int col = ks*16 + (((lane >> 3) & 1) << 3);
                uint32_t addr = (uint32_t)__cvta_generic_to_shared(&sB[row][col]);
                asm volatile("ldmatrix.sync.aligned.m8n8.x2.shared.b16 {%0,%1}, [%2];"
                    : "=r"(bF[nf][0]), "=r"(bF[nf][1]) : "r"(addr));
            }
            #pragma unroll
            for (int mf = 0; mf < 4; mf++)
                #pragma unroll
                for (int nf = 0; nf < 4; nf++) {
                    float* c = acc[mf][nf];
                    asm volatile("mma.sync.aligned.m16n8k16.row.col.f32.bf16.bf16.f32 "
                        "{%0,%1,%2,%3}, {%4,%5,%6,%7}, {%8,%9}, {%0,%1,%2,%3};"
                        : "+f"(c[0]), "+f"(c[1]), "+f"(c[2]), "+f"(c[3])
                        : "r"(aF[mf][0]), "r"(aF[mf][1]), "r"(aF[mf][2]), "r"(aF[mf][3]),
                          "r"(bF[nf][0]), "r"(bF[nf][1]));
                }
        }
    }

    float* gOut = g_bias[which];
    #pragma unroll
    for (int mf = 0; mf < 4; mf++)
        #pragma unroll
        for (int h = 0; h < 2; h++) {
            int row = iBase + wRow*64 + mf*16 + h*8 + (lane >> 2);
            #pragma unroll
            for (int nf = 0; nf < 4; nf++) {
                int col = jBase + wCol*32 + nf*8 + (lane & 3)*2;
                float2 v = make_float2(acc[mf][nf][h*2], acc[mf][nf][h*2+1]);
                *reinterpret_cast<float2*>(gOut + (size_t)row*NN + col) = v;
            }
        }
}

// ---------------------------------------------------------------------------
// Fused GEMM(K=384) + bias + block LSE partial. One 128x128 tile per CTA.
// Grid (128, 49): which=x&1, jt=(x>>1)&7, iTile=x>>4; s=y. 256 threads.
// 8 warps as 2 (i rows of 64) x 4 (j cols of 32); warp tile 64x32, 64 accs.
// 2 CTAs/SM (128 regs, 96KB smem) -> 16 warps/SM for latency hiding.
#define SLOT   32768                // A chunk 16KB + B chunk 16KB
#define OFF_DIAG 98304              // 128 floats
#define SMEM_MAIN 98816
// aliased onto slot 0 after its last read (chunk 3 consumed):
#define OFF_SM  0                   // 128*4 floats
#define OFF_SL  2048                // 128*4 floats

__global__ void __launch_bounds__(256, 2) k_main() {
    extern __shared__ char smraw[];
    const uint32_t sb = (uint32_t)__cvta_generic_to_shared(smraw);

    const int which = blockIdx.x & 1;
    const int jt    = (blockIdx.x >> 1) & 7;
    const int iTile = blockIdx.x >> 4;
    const int s     = blockIdx.y;
    const int tid   = threadIdx.x;
    const int lane  = tid & 31;
    const int warp  = tid >> 5;
    const int wRow  = warp >> 2;    // 0..1 (i groups of 64)
    const int wCol  = warp & 3;     // 0..3 (j groups of 32)
    const int iBase = iTile * 128;
    const int jBase = jt * 128;

    const __nv_bfloat16* gA = which ? (g_cur + ((size_t)(s*NN) + iBase) * CC)
                                    : (g_fs + (size_t)iBase * CC);
    const __nv_bfloat16* gB = g_prev + ((size_t)(s*NN) + jBase) * CC;
    const float* gBias = g_bias[which] + (size_t)iBase * NN + jBase;

    // chunk loader: A(128x64) + B(128x64) into slot c%3, one commit group
    auto loadAB = [&](int c) {
        int kt = c;
        uint32_t base = sb + (c % 3) * SLOT;
        #pragma unroll
        for (int p = 0; p < 4; ++p) {
            int id = tid + p * 256;
            int r = id >> 3, u = id & 7;
            uint32_t sw = r*128 + (((u ^ (r & 7))) << 4);
            cp16(base + sw,         gA + (size_t)r*CC + kt*64 + u*8);
            cp16(base + 16384 + sw, gB + (size_t)r*CC + kt*64 + u*8);
        }
        asm volatile("cp.async.commit_group;");
    };
    loadAB(0);
    loadAB(1);

    // per-thread ldmatrix row precompute
    const int lane15 = lane & 15;
    const int hi     = lane >> 4;
    int aOff[4], aXor[4], bOff[2], bXor[2];
    #pragma unroll
    for (int mf = 0; mf < 4; mf++) {
        int r = wRow*64 + mf*16 + lane15;
        aOff[mf] = r * 128; aXor[mf] = r & 7;
    }
    #pragma unroll
    for (int nfp = 0; nfp < 2; nfp++) {
        int r = wCol*32 + nfp*16 + lane15;
        bOff[nfp] = 16384 + r * 128; bXor[nfp] = r & 7;
    }

    float acc[4][4][4];
    #pragma unroll
    for (int mf = 0; mf < 4; mf++)
        #pragma unroll
        for (int nf = 0; nf < 4; nf++)
            #pragma unroll
            for (int v = 0; v < 4; v++) acc[mf][nf][v] = 0.f;

    for (int c = 0; c < 6; ++c) {
        if (c < 5) asm volatile("cp.async.wait_group 1;");
        else       asm volatile("cp.async.wait_group 0;");
        __syncthreads();
        // barrier => all warps done reading slot (c-1)%3 == (c+2)%3
        if (c + 2 < 6) loadAB(c + 2);

        const uint32_t base = sb + (c % 3) * SLOT;

        #pragma unroll
        for (int ks = 0; ks < 4; ++ks) {
            const int u = ks*2 + hi;
            uint32_t aF[4][4], bF[4][2];
            #pragma unroll
            for (int mf = 0; mf < 4; mf++) {
                uint32_t addr = base + aOff[mf] + ((u ^ aXor[mf]) << 4);
                asm volatile("ldmatrix.sync.aligned.m8n8.x4.shared.b16 {%0,%1,%2,%3}, [%4];"
                    : "=r"(aF[mf][0]), "=r"(aF[mf][1]), "=r"(aF[mf][2]), "=r"(aF[mf][3])
                    : "r"(addr));
            }
            #pragma unroll
            for (int nfp = 0; nfp < 2; nfp++) {
                uint32_t addr = base + bOff[nfp] + ((u ^ bXor[nfp]) << 4);
                uint32_t b0, b1, b2, b3;
                asm volatile("ldmatrix.sync.aligned.m8n8.x4.shared.b16 {%0,%1,%2,%3}, [%4];"
                    : "=r"(b0), "=r"(b1), "=r"(b2), "=r"(b3) : "r"(addr));
                bF[nfp*2][0] = b0; bF[nfp*2][1] = b2;
                bF[nfp*2+1][0] = b1; bF[nfp*2+1][1] = b3;
            }
            #pragma unroll
            for (int mf = 0; mf < 4; mf++)
                #pragma unroll
                for (int nf = 0; nf < 4; nf++) {
                    float* cc = acc[mf][nf];
                    asm volatile("mma.sync.aligned.m16n8k16.row.col.f32.bf16.bf16.f32 "
                        "{%0,%1,%2,%3}, {%4,%5,%6,%7}, {%8,%9}, {%0,%1,%2,%3};"
                        : "+f"(cc[0]), "+f"(cc[1]), "+f"(cc[2]), "+f"(cc[3])
                        : "r"(aF[mf][0]), "r"(aF[mf][1]), "r"(aF[mf][2]), "r"(aF[mf][3]),
                          "r"(bF[nf][0]), "r"(bF[nf][1]));
                }
        }
    }

    // ---- bias add (fp32 from L2)
    #pragma unroll
    for (int mf = 0; mf < 4; mf++)
        #pragma unroll
        for (int h = 0; h < 2; h++) {
            int row = wRow*64 + mf*16 + h*8 + (lane >> 2);
            const float2* bp = reinterpret_cast<const float2*>(
                gBias + (size_t)row*NN + wCol*32 + (lane & 3)*2);
            #pragma unroll
            for (int nf = 0; nf < 4; nf++) {
                float2 b = __ldg(bp + nf*4);
                acc[mf][nf][h*2]   += b.x;
                acc[mf][nf][h*2+1] += b.y;
            }
        }

    // ---- block LSE over this warp's 32 cols (single j-tile per CTA)
    float* sDiag = reinterpret_cast<float*>(smraw + OFF_DIAG);
    float* sM = reinterpret_cast<float*>(smraw + OFF_SM);   // aliases slot 0
    float* sL = reinterpret_cast<float*>(smraw + OFF_SL);
    const bool hasDiag = (iTile == jt);

    __syncthreads();   // all warps done with slot data; safe to alias slot 0

    #pragma unroll
    for (int mf = 0; mf < 4; mf++) {
        #pragma unroll
        for (int h = 0; h < 2; h++) {
            float tm = -3e38f;
            #pragma unroll
            for (int nf = 0; nf < 4; nf++)
                tm = fmaxf(tm, fmaxf(acc[mf][nf][h*2], acc[mf][nf][h*2+1]));
            tm = fmaxf(tm, __shfl_xor_sync(0xffffffffu, tm, 1));
            tm = fmaxf(tm, __shfl_xor_sync(0xffffffffu, tm, 2));
            float p = 0.f;
            #pragma unroll
            for (int nf = 0; nf < 4; nf++) {
                p += __expf(acc[mf][nf][h*2]   - tm);
                p += __expf(acc[mf][nf][h*2+1] - tm);
            }
            p += __shfl_xor_sync(0xffffffffu, p, 1);
            p += __shfl_xor_sync(0xffffffffu, p, 2);
            int rowLocal = wRow*64 + mf*16 + h*8 + (lane >> 2);
            if ((lane & 3) == 0) {
                sM[rowLocal*4 + wCol] = tm;
                sL[rowLocal*4 + wCol] = p;
            }
            if (hasDiag) {
                #pragma unroll
                for (int nf = 0; nf < 4; nf++) {
                    #pragma unroll
                    for (int q = 0; q < 2; q++) {
                        int col = wCol*32 + nf*8 + (lane & 3)*2 + q;
                        if (col == rowLocal) sDiag[rowLocal] = acc[mf][nf][h*2+q];
                    }
                }
            }
        }
    }
    __syncthreads();

    if (tid < 128) {
        float M = fmaxf(fmaxf(sM[tid*4+0], sM[tid*4+1]), fmaxf(sM[tid*4+2], sM[tid*4+3]));
        float L = 0.f;
        #pragma unroll
        for (int w = 0; w < 4; w++) L += sL[tid*4+w] * __expf(sM[tid*4+w] - M);
        size_t pidx = (((size_t)(which*SS + s)*8 + iTile)*128 + tid)*8 + jt;
        g_pm[pidx] = M;
        g_pl[pidx] = L;
        if (hasDiag)
            g_pd[(size_t)(which*SS + s)*NN + iBase + tid] = sDiag[tid];
    }
}

// ---------------------------------------------------------------------------
// combine 8 j-blocks: grid (98) = (which*49+s), 1024 threads = rows
__global__ void k_combine() {
    __shared__ float sr[32];
    const int ws = blockIdx.x;              // which*SS + s
    const int r  = threadIdx.x;             // 0..1023
    const int iTile = r >> 7, rowIn = r & 127;
    size_t base = (((size_t)ws*8 + iTile)*128 + rowIn)*8;
    float m[8], l[8];
    #pragma unroll
    for (int j = 0; j < 8; j++) { m[j] = g_pm[base+j]; l[j] = g_pl[base+j]; }
    float M = m[0];
    #pragma unroll
    for (int j = 1; j < 8; j++) M = fmaxf(M, m[j]);
    float L = 0.f;
    #pragma unroll
    for (int j = 0; j < 8; j++) L += l[j] * __expf(m[j] - M);
    float ce = M + logf(L) - g_pd[(size_t)ws*NN + r];
    #pragma unroll
    for (int o = 16; o > 0; o >>= 1) ce += __shfl_xor_sync(0xffffffffu, ce, o);
    if ((r & 31) == 0) sr[r >> 5] = ce;
    __syncthreads();
    if (r < 32) {
        float v = sr[r];
        #pragma unroll
        for (int o = 16; o > 0; o >>= 1) v += __shfl_xor_sync(0xffffffffu, v, o);
        if (r == 0) g_ce[ws] = v;
    }
}

__global__ void k_final(float* __restrict__ out) {
    int tid = threadIdx.x;
    float s = (tid < 2*SS) ? g_ce[tid] : 0.f;
    #pragma unroll
    for (int o = 16; o > 0; o >>= 1) s += __shfl_xor_sync(0xffffffffu, s, o);
    __shared__ float sr[4];
    if ((tid & 31) == 0) sr[tid >> 5] = s;
    __syncthreads();
    if (tid == 0) out[0] = (sr[0] + sr[1] + sr[2] + sr[3]) / (float)(SS * NN);
}

// ---------------------------------------------------------------------------
extern "C" void kernel_launch(void* const* d_in, const int* in_sizes, int n_in,
                              void* d_out, int out_size) {
    const float* f  = (const float*)d_in[0];
    const float* xc = (const float*)d_in[1];
    const float* xp = (const float*)d_in[2];
    const float* mt = (const float*)d_in[3];
    const float* mp = (const float*)d_in[4];
    const float* ct = (const float*)d_in[5];
    const float* cp = (const float*)d_in[6];
    float* out = (float*)d_out;

    cudaFuncSetAttribute(k_main, cudaFuncAttributeMaxDynamicSharedMemorySize, SMEM_MAIN);

    k_convert_f<<<(NN*DD + 255)/256, 256>>>(f);
    k_mc<<<NN, 128>>>(mp, cp, mt, ct);
    k_spatial<<<dim3(NN, 2), 256>>>(xc, xp, out);
    k_bias<<<dim3(8, 8, 2), 256>>>();
    k_main<<<dim3(128, SS), 256, SMEM_MAIN>>>();
    k_combine<<<2*SS, 1024>>>();
    k_final<<<1, 128>>>(out);
}

// round 16
// speedup vs baseline: 1.5688x; 1.0148x over previous
#include <cuda_runtime.h>
#include <cuda_bf16.h>
#include <cstdint>

#define NN 1024
#define DD 512
#define CC 384
#define SS 49
#define NCS (NN*CC*SS)   // 19267584

// scratch (static device arrays — no runtime allocation)
__device__ __align__(16) __nv_bfloat16 g_fs[NN*CC];              // f[:,0:384]
__device__ __align__(16) __nv_bfloat16 g_fm[NN*128];             // f[:,384:512]
__device__ __align__(16) __nv_bfloat16 g_prev[(size_t)SS*NN*CC]; // pos spatial
__device__ __align__(16) __nv_bfloat16 g_cur[(size_t)SS*NN*CC];  // pred spatial
__device__ __align__(16) __nv_bfloat16 g_mcp[NN*128];            // [m_prev,c_prev]
__device__ __align__(16) __nv_bfloat16 g_mcc[NN*128];            // [m_t,c_t]
__device__ __align__(4) __nv_bfloat16 g_biasb[2][NN*NN];         // 4MB bf16
__device__ float g_pm[(size_t)2*SS*8*128*8];                     // block max per jt
__device__ float g_pl[(size_t)2*SS*8*128*8];                     // block sumexp per jt
__device__ float g_pd[2*SS*NN];                                  // diag
__device__ float g_ce[2*SS];

__device__ __forceinline__ void cp16(uint32_t dst, const void* src) {
    asm volatile("cp.async.cg.shared.global [%0], [%1], 16;\n" :: "r"(dst), "l"(src));
}

// ---------------------------------------------------------------------------
// convert f (split) + mc tables, one launch. grid: 1024 blocks, 128 threads.
__global__ void k_prep(const float* __restrict__ f,
                       const float* __restrict__ mp, const float* __restrict__ cp,
                       const float* __restrict__ mt, const float* __restrict__ ct) {
    int j = blockIdx.x;
    int dd = threadIdx.x;  // 0..127
    #pragma unroll
    for (int p = 0; p < 4; p++) {
        int d = dd + p*128;
        __nv_bfloat16 v = __float2bfloat16(f[(size_t)j*DD + d]);
        if (d < CC) g_fs[j*CC + d] = v; else g_fm[j*128 + d - CC] = v;
    }
    float vp = (dd < 64) ? mp[j*64 + dd] : cp[j*64 + dd - 64];
    float vc = (dd < 64) ? mt[j*64 + dd] : ct[j*64 + dd - 64];
    g_mcp[j*128 + dd] = __float2bfloat16(vp);
    g_mcc[j*128 + dd] = __float2bfloat16(vc);
}

// dst[s][j][d] = x[j][d][s] (d<384), bf16; also raw fp32 copy. grid (1024,2)
__global__ void k_spatial(const float* __restrict__ xc,
                          const float* __restrict__ xp,
                          float* __restrict__ out) {
    __shared__ float sbuf[32*SS];
    const int isPred = blockIdx.y;
    const float* x = isPred ? xc : xp;
    __nv_bfloat16* dst = isPred ? g_cur : g_prev;
    float* outCopy = out + 1 + (size_t)isPred*NCS;
    int j = blockIdx.x;
    const float* xj = x + (size_t)j*CC*SS;
    float* oj = outCopy + (size_t)j*CC*SS;
    for (int d0 = 0; d0 < CC; d0 += 32) {
        for (int t = threadIdx.x; t < 32*SS; t += blockDim.x) {
            float v = xj[d0*SS + t];
            sbuf[t] = v;
            oj[d0*SS + t] = v;
        }
        __syncthreads();
        for (int t = threadIdx.x; t < 32*SS; t += blockDim.x) {
            int ss = t >> 5;
            int dd = t & 31;
            dst[((size_t)(ss*NN + j))*CC + d0 + dd] = __float2bfloat16(sbuf[dd*SS + ss]);
        }
        __syncthreads();
    }
}

// ---------------------------------------------------------------------------
// bias[which][i][j] = (which? mcc[i] : fm[i]) . mcp[j], K=128, bf16 out.
__global__ void __launch_bounds__(256) k_bias() {
    const int iBase = blockIdx.x * 128;
    const int jBase = blockIdx.y * 128;
    const int which = blockIdx.z;
    const int tid  = threadIdx.x;
    const int lane = tid & 31;
    const int warp = tid >> 5;
    const int wRow = warp >> 2;
    const int wCol = warp & 3;

    __shared__ __align__(16) __nv_bfloat16 sA[128][72];
    __shared__ __align__(16) __nv_bfloat16 sB[128][72];

    const __nv_bfloat16* gA = (which ? g_mcc : g_fm) + (size_t)iBase * 128;
    const __nv_bfloat16* gB = g_mcp + (size_t)jBase * 128;

    float acc[4][4][4];
    #pragma unroll
    for (int mf = 0; mf < 4; mf++)
        #pragma unroll
        for (int nf = 0; nf < 4; nf++)
            #pragma unroll
            for (int v = 0; v < 4; v++) acc[mf][nf][v] = 0.f;

    for (int kt = 0; kt < 2; ++kt) {
        __syncthreads();
        #pragma unroll
        for (int p = 0; p < 4; ++p) {
            int id = tid + p * 256;
            int r  = id >> 3;
            int ck = id & 7;
            *reinterpret_cast<int4*>(&sA[r][ck*8]) =
                *(reinterpret_cast<const int4*>(gA + (size_t)r*128 + kt*64) + ck);
            *reinterpret_cast<int4*>(&sB[r][ck*8]) =
                *(reinterpret_cast<const int4*>(gB + (size_t)r*128 + kt*64) + ck);
        }
        __syncthreads();
        #pragma unroll
        for (int ks = 0; ks < 4; ++ks) {
            uint32_t aF[4][4], bF[4][2];
            #pragma unroll
            for (int mf = 0; mf < 4; mf++) {
                int row = wRow*64 + mf*16 + (lane & 15);
                int col = ks*16 + ((lane >> 4) << 3);
                uint32_t addr = (uint32_t)__cvta_generic_to_shared(&sA[row][col]);
                asm volatile("ldmatrix.sync.aligned.m8n8.x4.shared.b16 {%0,%1,%2,%3}, [%4];"
                    : "=r"(aF[mf][0]), "=r"(aF[mf][1]), "=r"(aF[mf][2]), "=r"(aF[mf][3])
                    : "r"(addr));
            }
            #pragma unroll
            for (int nf = 0; nf < 4; nf++) {
                int row = wCol*32 + nf*8 + (lane & 7);
                int col = ks*16 + (((lane >> 3) & 1) << 3);
                uint32_t addr = (uint32_t)__cvta_generic_to_shared(&sB[row][col]);
                asm volatile("ldmatrix.sync.aligned.m8n8.x2.shared.b16 {%0,%1}, [%2];"
                    : "=r"(bF[nf][0]), "=r"(bF[nf][1]) : "r"(addr));
            }
            #pragma unroll
            for (int mf = 0; mf < 4; mf++)
                #pragma unroll
                for (int nf = 0; nf < 4; nf++) {
                    float* c = acc[mf][nf];
                    asm volatile("mma.sync.aligned.m16n8k16.row.col.f32.bf16.bf16.f32 "
                        "{%0,%1,%2,%3}, {%4,%5,%6,%7}, {%8,%9}, {%0,%1,%2,%3};"
                        : "+f"(c[0]), "+f"(c[1]), "+f"(c[2]), "+f"(c[3])
                        : "r"(aF[mf][0]), "r"(aF[mf][1]), "r"(aF[mf][2]), "r"(aF[mf][3]),
                          "r"(bF[nf][0]), "r"(bF[nf][1]));
                }
        }
    }

    __nv_bfloat16* gOut = g_biasb[which];
    #pragma unroll
    for (int mf = 0; mf < 4; mf++)
        #pragma unroll
        for (int h = 0; h < 2; h++) {
            int row = iBase + wRow*64 + mf*16 + h*8 + (lane >> 2);
            #pragma unroll
            for (int nf = 0; nf < 4; nf++) {
                int col = jBase + wCol*32 + nf*8 + (lane & 3)*2;
                __nv_bfloat162 v = __floats2bfloat162_rn(acc[mf][nf][h*2],
                                                          acc[mf][nf][h*2+1]);
                *reinterpret_cast<__nv_bfloat162*>(gOut + (size_t)row*NN + col) = v;
            }
        }
}

// ---------------------------------------------------------------------------
// Fused GEMM(K=384) + bias + block LSE partial. One 128x128 tile per CTA.
// Grid (128, 49): which=x&1, jt=(x>>1)&7, iTile=x>>4; s=y. 256 threads.
// 8 warps as 2 (i rows of 64) x 4 (j cols of 32); warp tile 64x32, 64 accs.
// 2 CTAs/SM (128 regs, 96KB smem) -> 16 warps/SM for latency hiding.
#define SLOT   32768                // A chunk 16KB + B chunk 16KB
#define OFF_DIAG 98304              // 128 floats
#define SMEM_MAIN 98816
// aliased onto slot 0 after its last read (chunk 3 consumed):
#define OFF_SM  0                   // 128*4 floats
#define OFF_SL  2048                // 128*4 floats

__global__ void __launch_bounds__(256, 2) k_main() {
    extern __shared__ char smraw[];
    const uint32_t sb = (uint32_t)__cvta_generic_to_shared(smraw);

    const int which = blockIdx.x & 1;
    const int jt    = (blockIdx.x >> 1) & 7;
    const int iTile = blockIdx.x >> 4;
    const int s     = blockIdx.y;
    const int tid   = threadIdx.x;
    const int lane  = tid & 31;
    const int warp  = tid >> 5;
    const int wRow  = warp >> 2;    // 0..1 (i groups of 64)
    const int wCol  = warp & 3;     // 0..3 (j groups of 32)
    const int iBase = iTile * 128;
    const int jBase = jt * 128;

    const __nv_bfloat16* gA = which ? (g_cur + ((size_t)(s*NN) + iBase) * CC)
                                    : (g_fs + (size_t)iBase * CC);
    const __nv_bfloat16* gB = g_prev + ((size_t)(s*NN) + jBase) * CC;
    const __nv_bfloat16* gBias = g_biasb[which] + (size_t)iBase * NN + jBase;

    // chunk loader: A(128x64) + B(128x64) into slot c%3, one commit group
    auto loadAB = [&](int c) {
        int kt = c;
        uint32_t base = sb + (c % 3) * SLOT;
        #pragma unroll
        for (int p = 0; p < 4; ++p) {
            int id = tid + p * 256;
            int r = id >> 3, u = id & 7;
            uint32_t sw = r*128 + (((u ^ (r & 7))) << 4);
            cp16(base + sw,         gA + (size_t)r*CC + kt*64 + u*8);
            cp16(base + 16384 + sw, gB + (size_t)r*CC + kt*64 + u*8);
        }
        asm volatile("cp.async.commit_group;");
    };
    loadAB(0);
    loadAB(1);

    // per-thread ldmatrix row precompute
    const int lane15 = lane & 15;
    const int hi     = lane >> 4;
    int aOff[4], aXor[4], bOff[2], bXor[2];
    #pragma unroll
    for (int mf = 0; mf < 4; mf++) {
        int r = wRow*64 + mf*16 + lane15;
        aOff[mf] = r * 128; aXor[mf] = r & 7;
    }
    #pragma unroll
    for (int nfp = 0; nfp < 2; nfp++) {
        int r = wCol*32 + nfp*16 + lane15;
        bOff[nfp] = 16384 + r * 128; bXor[nfp] = r & 7;
    }

    float acc[4][4][4];
    #pragma unroll
    for (int mf = 0; mf < 4; mf++)
        #pragma unroll
        for (int nf = 0; nf < 4; nf++)
            #pragma unroll
            for (int v = 0; v < 4; v++) acc[mf][nf][v] = 0.f;

    for (int c = 0; c < 6; ++c) {
        if (c < 5) asm volatile("cp.async.wait_group 1;");
        else       asm volatile("cp.async.wait_group 0;");
        __syncthreads();
        // barrier => all warps done reading slot (c-1)%3 == (c+2)%3
        if (c + 2 < 6) loadAB(c + 2);

        const uint32_t base = sb + (c % 3) * SLOT;

        #pragma unroll
        for (int ks = 0; ks < 4; ++ks) {
            const int u = ks*2 + hi;
            uint32_t aF[4][4], bF[4][2];
            #pragma unroll
            for (int mf = 0; mf < 4; mf++) {
                uint32_t addr = base + aOff[mf] + ((u ^ aXor[mf]) << 4);
                asm volatile("ldmatrix.sync.aligned.m8n8.x4.shared.b16 {%0,%1,%2,%3}, [%4];"
                    : "=r"(aF[mf][0]), "=r"(aF[mf][1]), "=r"(aF[mf][2]), "=r"(aF[mf][3])
                    : "r"(addr));
            }
            #pragma unroll
            for (int nfp = 0; nfp < 2; nfp++) {
                uint32_t addr = base + bOff[nfp] + ((u ^ bXor[nfp]) << 4);
                uint32_t b0, b1, b2, b3;
                asm volatile("ldmatrix.sync.aligned.m8n8.x4.shared.b16 {%0,%1,%2,%3}, [%4];"
                    : "=r"(b0), "=r"(b1), "=r"(b2), "=r"(b3) : "r"(addr));
                bF[nfp*2][0] = b0; bF[nfp*2][1] = b2;
                bF[nfp*2+1][0] = b1; bF[nfp*2+1][1] = b3;
            }
            #pragma unroll
            for (int mf = 0; mf < 4; mf++)
                #pragma unroll
                for (int nf = 0; nf < 4; nf++) {
                    float* cc = acc[mf][nf];
                    asm volatile("mma.sync.aligned.m16n8k16.row.col.f32.bf16.bf16.f32 "
                        "{%0,%1,%2,%3}, {%4,%5,%6,%7}, {%8,%9}, {%0,%1,%2,%3};"
                        : "+f"(cc[0]), "+f"(cc[1]), "+f"(cc[2]), "+f"(cc[3])
                        : "r"(aF[mf][0]), "r"(aF[mf][1]), "r"(aF[mf][2]), "r"(aF[mf][3]),
                          "r"(bF[nf][0]), "r"(bF[nf][1]));
                }
        }
    }

    // ---- bias add (bf16 from L2)
    #pragma unroll
    for (int mf = 0; mf < 4; mf++)
        #pragma unroll
        for (int h = 0; h < 2; h++) {
            int row = wRow*64 + mf*16 + h*8 + (lane >> 2);
            const __nv_bfloat162* bp = reinterpret_cast<const __nv_bfloat162*>(
                gBias + (size_t)row*NN + wCol*32 + (lane & 3)*2);
            #pragma unroll
            for (int nf = 0; nf < 4; nf++) {
                float2 b = __bfloat1622float2(__ldg(bp + nf*4));
                acc[mf][nf][h*2]   += b.x;
                acc[mf][nf][h*2+1] += b.y;
            }
        }

    // ---- block LSE over this warp's 32 cols (single j-tile per CTA)
    float* sDiag = reinterpret_cast<float*>(smraw + OFF_DIAG);
    float* sM = reinterpret_cast<float*>(smraw + OFF_SM);   // aliases slot 0
    float* sL = reinterpret_cast<float*>(smraw + OFF_SL);
    const bool hasDiag = (iTile == jt);

    __syncthreads();   // all warps done with slot data; safe to alias slot 0

    #pragma unroll
    for (int mf = 0; mf < 4; mf++) {
        #pragma unroll
        for (int h = 0; h < 2; h++) {
            float tm = -3e38f;
            #pragma unroll
            for (int nf = 0; nf < 4; nf++)
                tm = fmaxf(tm, fmaxf(acc[mf][nf][h*2], acc[mf][nf][h*2+1]));
            tm = fmaxf(tm, __shfl_xor_sync(0xffffffffu, tm, 1));
            tm = fmaxf(tm, __shfl_xor_sync(0xffffffffu, tm, 2));
            float p = 0.f;
            #pragma unroll
            for (int nf = 0; nf < 4; nf++) {
                p += __expf(acc[mf][nf][h*2]   - tm);
                p += __expf(acc[mf][nf][h*2+1] - tm);
            }
            p += __shfl_xor_sync(0xffffffffu, p, 1);
            p += __shfl_xor_sync(0xffffffffu, p, 2);
            int rowLocal = wRow*64 + mf*16 + h*8 + (lane >> 2);
            if ((lane & 3) == 0) {
                sM[rowLocal*4 + wCol] = tm;
                sL[rowLocal*4 + wCol] = p;
            }
            if (hasDiag) {
                #pragma unroll
                for (int nf = 0; nf < 4; nf++) {
                    #pragma unroll
                    for (int q = 0; q < 2; q++) {
                        int col = wCol*32 + nf*8 + (lane & 3)*2 + q;
                        if (col == rowLocal) sDiag[rowLocal] = acc[mf][nf][h*2+q];
                    }
                }
            }
        }
    }
    __syncthreads();

    if (tid < 128) {
        float M = fmaxf(fmaxf(sM[tid*4+0], sM[tid*4+1]), fmaxf(sM[tid*4+2], sM[tid*4+3]));
        float L = 0.f;
        #pragma unroll
        for (int w = 0; w < 4; w++) L += sL[tid*4+w] * __expf(sM[tid*4+w] - M);
        size_t pidx = (((size_t)(which*SS + s)*8 + iTile)*128 + tid)*8 + jt;
        g_pm[pidx] = M;
        g_pl[pidx] = L;
        if (hasDiag)
            g_pd[(size_t)(which*SS + s)*NN + iBase + tid] = sDiag[tid];
    }
}

// ---------------------------------------------------------------------------
// combine 8 j-blocks: grid (98) = (which*49+s), 1024 threads = rows
__global__ void k_combine() {
    __shared__ float sr[32];
    const int ws = blockIdx.x;              // which*SS + s
    const int r  = threadIdx.x;             // 0..1023
    const int iTile = r >> 7, rowIn = r & 127;
    size_t base = (((size_t)ws*8 + iTile)*128 + rowIn)*8;
    float m[8], l[8];
    #pragma unroll
    for (int j = 0; j < 8; j++) { m[j] = g_pm[base+j]; l[j] = g_pl[base+j]; }
    float M = m[0];
    #pragma unroll
    for (int j = 1; j < 8; j++) M = fmaxf(M, m[j]);
    float L = 0.f;
    #pragma unroll
    for (int j = 0; j < 8; j++) L += l[j] * __expf(m[j] - M);
    float ce = M + logf(L) - g_pd[(size_t)ws*NN + r];
    #pragma unroll
    for (int o = 16; o > 0; o >>= 1) ce += __shfl_xor_sync(0xffffffffu, ce, o);
    if ((r & 31) == 0) sr[r >> 5] = ce;
    __syncthreads();
    if (r < 32) {
        float v = sr[r];
        #pragma unroll
        for (int o = 16; o > 0; o >>= 1) v += __shfl_xor_sync(0xffffffffu, v, o);
        if (r == 0) g_ce[ws] = v;
    }
}

__global__ void k_final(float* __restrict__ out) {
    int tid = threadIdx.x;
    float s = (tid < 2*SS) ? g_ce[tid] : 0.f;
    #pragma unroll
    for (int o = 16; o > 0; o >>= 1) s += __shfl_xor_sync(0xffffffffu, s, o);
    __shared__ float sr[4];
    if ((tid & 31) == 0) sr[tid >> 5] = s;
    __syncthreads();
    if (tid == 0) out[0] = (sr[0] + sr[1] + sr[2] + sr[3]) / (float)(SS * NN);
}

// ---------------------------------------------------------------------------
extern "C" void kernel_launch(void* const* d_in, const int* in_sizes, int n_in,
                              void* d_out, int out_size) {
    const float* f  = (const float*)d_in[0];
    const float* xc = (const float*)d_in[1];
    const float* xp = (const float*)d_in[2];
    const float* mt = (const float*)d_in[3];
    const float* mp = (const float*)d_in[4];
    const float* ct = (const float*)d_in[5];
    const float* cp = (const float*)d_in[6];
    float* out = (float*)d_out;

    cudaFuncSetAttribute(k_main, cudaFuncAttributeMaxDynamicSharedMemorySize, SMEM_MAIN);

    k_prep<<<NN, 128>>>(f, mp, cp, mt, ct);
    k_bias<<<dim3(8, 8, 2), 256>>>();
    k_spatial<<<dim3(NN, 2), 256>>>(xc, xp, out);
    k_main<<<dim3(128, SS), 256, SMEM_MAIN>>>();
    k_combine<<<2*SS, 1024>>>();
    k_final<<<1, 128>>>(out);
}